// round 1
// baseline (speedup 1.0000x reference)
#include <cuda_runtime.h>
#include <cuda_bf16.h>

// Problem constants (from reference)
#define N_IN    1024
#define BATCH   1024
#define DEG     32
#define N_LAYERS 9
#define TOTAL_COLS 18432      // 1024 + 8*2048 + 1024
#define OUT_COL_BASE 17408    // first column of the last layer

// Column-major value buffer: g_vals[col * BATCH + b]. 75.5 MB static scratch.
__device__ float g_vals[TOTAL_COLS * BATCH];

// ---------------------------------------------------------------------------
// Transpose X (BATCH x N_IN row-major) into g_vals column-major.
// grid (32, 32), block (32, 8)
// ---------------------------------------------------------------------------
__global__ void transpose_in_kernel(const float* __restrict__ X) {
    __shared__ float tile[32][33];
    int bx = blockIdx.x * 32;   // column (feature) tile base
    int by = blockIdx.y * 32;   // row (batch) tile base
    int tx = threadIdx.x, ty = threadIdx.y;

    #pragma unroll
    for (int i = 0; i < 32; i += 8) {
        // read X[b][c], b = by+ty+i, c = bx+tx (coalesced on c)
        tile[ty + i][tx] = X[(by + ty + i) * N_IN + (bx + tx)];
    }
    __syncthreads();
    #pragma unroll
    for (int i = 0; i < 32; i += 8) {
        // write g_vals[c][b], c = bx+ty+i, b = by+tx (coalesced on b)
        g_vals[(bx + ty + i) * BATCH + (by + tx)] = tile[tx][ty + i];
    }
}

// ---------------------------------------------------------------------------
// One layer: block j computes neuron j of this layer for all 1024 batch elems.
// Each of 256 threads owns 4 consecutive batch elements (float4).
// g_vals[col_base + j][:] = tanh(w * sum_k g_vals[idx[j][k]][:])
// ---------------------------------------------------------------------------
__global__ void __launch_bounds__(256) layer_kernel(
    const int* __restrict__ child_idx,  // base of this layer's [sz][DEG] block
    const float* __restrict__ w_ptr,
    int col_base)
{
    int j = blockIdx.x;
    int t = threadIdx.x;  // 0..255

    __shared__ int sidx[DEG];
    if (t < DEG) sidx[t] = child_idx[j * DEG + t];
    __syncthreads();

    const float4* vals4 = reinterpret_cast<const float4*>(g_vals);

    float4 acc0 = make_float4(0.f, 0.f, 0.f, 0.f);
    float4 acc1 = make_float4(0.f, 0.f, 0.f, 0.f);

    // Fully unrolled: 32 independent LDG.128 for deep MLP against L2 latency.
    #pragma unroll
    for (int k = 0; k < DEG; k += 2) {
        float4 v0 = vals4[(size_t)sidx[k]     * (BATCH / 4) + t];
        float4 v1 = vals4[(size_t)sidx[k + 1] * (BATCH / 4) + t];
        acc0.x += v0.x; acc0.y += v0.y; acc0.z += v0.z; acc0.w += v0.w;
        acc1.x += v1.x; acc1.y += v1.y; acc1.z += v1.z; acc1.w += v1.w;
    }

    float w = __ldg(w_ptr);
    float4 out;
    out.x = tanhf(w * (acc0.x + acc1.x));
    out.y = tanhf(w * (acc0.y + acc1.y));
    out.z = tanhf(w * (acc0.z + acc1.z));
    out.w = tanhf(w * (acc0.w + acc1.w));

    reinterpret_cast<float4*>(g_vals)[(size_t)(col_base + j) * (BATCH / 4) + t] = out;
}

// ---------------------------------------------------------------------------
// Transpose last 1024 columns (column-major) into d_out (BATCH x 1024 row-major).
// grid (32, 32), block (32, 8)
// ---------------------------------------------------------------------------
__global__ void transpose_out_kernel(float* __restrict__ out) {
    __shared__ float tile[32][33];
    int b0 = blockIdx.x * 32;   // batch tile base
    int c0 = blockIdx.y * 32;   // output-column tile base
    int tx = threadIdx.x, ty = threadIdx.y;

    #pragma unroll
    for (int i = 0; i < 32; i += 8) {
        // read g_vals[OUT_COL_BASE + c][b], c = c0+ty+i, b = b0+tx (coalesced on b)
        tile[ty + i][tx] = g_vals[(size_t)(OUT_COL_BASE + c0 + ty + i) * BATCH + (b0 + tx)];
    }
    __syncthreads();
    #pragma unroll
    for (int i = 0; i < 32; i += 8) {
        // write out[b][c], b = b0+ty+i, c = c0+tx (coalesced on c)
        out[(size_t)(b0 + ty + i) * 1024 + (c0 + tx)] = tile[tx][ty + i];
    }
}

// ---------------------------------------------------------------------------
extern "C" void kernel_launch(void* const* d_in, const int* in_sizes, int n_in,
                              void* d_out, int out_size) {
    const float* X         = (const float*)d_in[0];
    const float* w         = (const float*)d_in[1];
    const int*   child_idx = (const int*)d_in[2];
    float*       out       = (float*)d_out;

    (void)in_sizes; (void)n_in; (void)out_size;

    dim3 tgrid(32, 32), tblock(32, 8);
    transpose_in_kernel<<<tgrid, tblock>>>(X);

    static const int layer_sizes[N_LAYERS] =
        {2048, 2048, 2048, 2048, 2048, 2048, 2048, 2048, 1024};

    int idx_base = 0;
    int col_base = N_IN;
    for (int li = 0; li < N_LAYERS; li++) {
        int sz = layer_sizes[li];
        layer_kernel<<<sz, 256>>>(child_idx + (size_t)idx_base * DEG, w, col_base);
        idx_base += sz;
        col_base += sz;
    }

    transpose_out_kernel<<<tgrid, tblock>>>(out);
}